// round 2
// baseline (speedup 1.0000x reference)
#include <cuda_runtime.h>
#include <math.h>
#include <mma.h>

using namespace nvcuda;

#define G 1024
#define NNODE 256
#define FIN 128
#define DH 256

// ---------------- scratch (device globals; no allocations allowed) -------------
__device__ float g_norm0[G * NNODE];
__device__ float g_H  [G * NNODE * DH];   // layer0: (x*norm)@W0
__device__ float g_X1 [G * NNODE * DH];   // layer0 conv output
__device__ float g_Xp1[G * 32 * DH];
__device__ float g_A1 [G * 32 * 32];
__device__ float g_norm1[G * 32];
__device__ float g_H1 [G * 32 * DH];
__device__ float g_X2 [G * 32 * DH];
__device__ float g_Xp2[G * 16 * DH];
__device__ float g_A2 [G * 16 * 16];
__device__ float g_norm2[G * 16];
__device__ float g_H2 [G * 16 * DH];
__device__ float g_X3 [G * 16 * DH];
__device__ float g_Xp3[G * 8 * DH];
__device__ float g_read[G * 1536];
__device__ float g_h  [G * 128];

// ---------------- degree -> norm for the initial adjacency ---------------------
__global__ void degnorm_kernel(const float* __restrict__ adj, float* __restrict__ nrm)
{
    int row = blockIdx.x * 8 + (threadIdx.x >> 5);
    int lane = threadIdx.x & 31;
    const float* a = adj + (long)row * 256;
    float s = 0.f;
#pragma unroll
    for (int q = 0; q < 8; q++) s += a[lane + 32 * q];
#pragma unroll
    for (int sh = 16; sh > 0; sh >>= 1) s += __shfl_down_sync(0xffffffffu, s, sh);
    if (lane == 0) nrm[row] = rsqrtf(fmaxf(s, 1.f));
}

// =============== TF32 tensor-core GEMM with error-compensated split ============
// C[g] = epilogue( (rowscaleA .* A[g]) @ B[g] )
// SPLIT_A == 1: A split hi/lo (3 mma chains: Ah*Bh + Ah*Bl + Al*Bh)  ~fp32 acc.
// SPLIT_A == 0: A exact in tf32 (e.g. binary adjacency); 2 chains: A*Bh + A*Bl.
// BM=128, BN=128, BK=16, 256 threads (8 warps in 2x4), warp tile 64x32.
template <int SPLIT_A>
__global__ void tf32gemm_kernel(const float* __restrict__ A, const float* __restrict__ B,
                                float* __restrict__ C,
                                int M, int N, int K,
                                long bA, long bB, long bC,
                                const float* __restrict__ rsA,
                                const float* __restrict__ rsC, int rsCstride,
                                const float* __restrict__ bias, int leaky)
{
    int g = blockIdx.z;
    const float* Ag = A + (long)g * bA;
    const float* Bg = B + (long)g * bB;
    float* Cg = C + (long)g * bC;
    const float* rsCg = rsC ? rsC + (long)g * rsCstride : nullptr;

    int bm = blockIdx.y * 128;
    int bn = blockIdx.x * 128;

    __shared__ float sAh[128][20];
    __shared__ float sAl[128][20];
    __shared__ float sBh[16][132];
    __shared__ float sBl[16][132];
    __shared__ float sCst[8][16][20];

    int tid = threadIdx.x;
    int warp = tid >> 5;
    int lane = tid & 31;
    int wm = warp >> 2;   // 0..1
    int wn = warp & 3;    // 0..3

    wmma::fragment<wmma::accumulator, 16, 16, 8, float> acc[4][2];
#pragma unroll
    for (int i = 0; i < 4; i++)
#pragma unroll
        for (int j = 0; j < 2; j++) wmma::fill_fragment(acc[i][j], 0.f);

    for (int k0 = 0; k0 < K; k0 += 16) {
        // ---- load A tile 128x16 (rowscale + tf32 split) ----
#pragma unroll
        for (int it = 0; it < 2; it++) {
            int idx = tid * 4 + it * 1024;
            int r = idx >> 4, c = idx & 15;
            float4 v = *(const float4*)(Ag + (long)(bm + r) * K + k0 + c);
            if (rsA) {
                float sc = rsA[(long)g * 0 + bm + r]; // flat-M rowscale (g folded into M)
                // batched variant uses per-graph rsC only; rsA used flat
                sc = rsA[bm + r + (bA ? 0 : 0)];
                sc = rsA[(bA ? (g * M + bm + r) : (bm + r))];
                v.x *= sc; v.y *= sc; v.z *= sc; v.w *= sc;
            }
            if (SPLIT_A) {
                float h0 = wmma::__float_to_tf32(v.x);
                float h1 = wmma::__float_to_tf32(v.y);
                float h2 = wmma::__float_to_tf32(v.z);
                float h3 = wmma::__float_to_tf32(v.w);
                sAh[r][c + 0] = h0; sAl[r][c + 0] = wmma::__float_to_tf32(v.x - h0);
                sAh[r][c + 1] = h1; sAl[r][c + 1] = wmma::__float_to_tf32(v.y - h1);
                sAh[r][c + 2] = h2; sAl[r][c + 2] = wmma::__float_to_tf32(v.z - h2);
                sAh[r][c + 3] = h3; sAl[r][c + 3] = wmma::__float_to_tf32(v.w - h3);
            } else {
                sAh[r][c + 0] = v.x; sAh[r][c + 1] = v.y;
                sAh[r][c + 2] = v.z; sAh[r][c + 3] = v.w;
            }
        }
        // ---- load B tile 16x128 (tf32 split) ----
#pragma unroll
        for (int it = 0; it < 2; it++) {
            int idx = tid * 4 + it * 1024;
            int r = idx >> 7, c = idx & 127;
            float4 v = *(const float4*)(Bg + (long)(k0 + r) * N + bn + c);
            float h0 = wmma::__float_to_tf32(v.x);
            float h1 = wmma::__float_to_tf32(v.y);
            float h2 = wmma::__float_to_tf32(v.z);
            float h3 = wmma::__float_to_tf32(v.w);
            sBh[r][c + 0] = h0; sBl[r][c + 0] = wmma::__float_to_tf32(v.x - h0);
            sBh[r][c + 1] = h1; sBl[r][c + 1] = wmma::__float_to_tf32(v.y - h1);
            sBh[r][c + 2] = h2; sBl[r][c + 2] = wmma::__float_to_tf32(v.z - h2);
            sBh[r][c + 3] = h3; sBl[r][c + 3] = wmma::__float_to_tf32(v.w - h3);
        }
        __syncthreads();

#pragma unroll
        for (int kk = 0; kk < 16; kk += 8) {
            wmma::fragment<wmma::matrix_a, 16, 16, 8, wmma::precision::tf32, wmma::row_major> ah[4], al[4];
            wmma::fragment<wmma::matrix_b, 16, 16, 8, wmma::precision::tf32, wmma::row_major> bh[2], bl[2];
#pragma unroll
            for (int i = 0; i < 4; i++) {
                wmma::load_matrix_sync(ah[i], &sAh[wm * 64 + i * 16][kk], 20);
                if (SPLIT_A) wmma::load_matrix_sync(al[i], &sAl[wm * 64 + i * 16][kk], 20);
            }
#pragma unroll
            for (int j = 0; j < 2; j++) {
                wmma::load_matrix_sync(bh[j], &sBh[kk][wn * 32 + j * 16], 132);
                wmma::load_matrix_sync(bl[j], &sBl[kk][wn * 32 + j * 16], 132);
            }
#pragma unroll
            for (int i = 0; i < 4; i++)
#pragma unroll
                for (int j = 0; j < 2; j++) {
                    wmma::mma_sync(acc[i][j], ah[i], bh[j], acc[i][j]);
                    wmma::mma_sync(acc[i][j], ah[i], bl[j], acc[i][j]);
                    if (SPLIT_A) wmma::mma_sync(acc[i][j], al[i], bh[j], acc[i][j]);
                }
        }
        __syncthreads();
    }

    // ---- epilogue via per-warp smem staging ----
#pragma unroll
    for (int i = 0; i < 4; i++)
#pragma unroll
        for (int j = 0; j < 2; j++) {
            wmma::store_matrix_sync(&sCst[warp][0][0], acc[i][j], 20, wmma::mem_row_major);
            __syncwarp();
#pragma unroll
            for (int e = 0; e < 8; e++) {
                int idx = lane + e * 32;
                int r = idx >> 4, c = idx & 15;
                int row = bm + wm * 64 + i * 16 + r;
                int col = bn + wn * 32 + j * 16 + c;
                float v = sCst[warp][r][c];
                if (rsC) v *= rsCg[row];
                if (bias) v += bias[col];
                if (leaky) v = (v > 0.f) ? v : 0.01f * v;
                Cg[(long)row * N + col] = v;
            }
            __syncwarp();
        }
}

// ---------------- fp32 tiled SGEMM (kept for the small MLP head GEMM) ----------
#define BM 128
#define BN 128
#define BK 8

__global__ void sgemm_kernel(const float* __restrict__ A, const float* __restrict__ B,
                             float* __restrict__ C,
                             int M, int N, int K,
                             long bA, long bB, long bC,
                             const float* __restrict__ rsA, int rsAstride,
                             const float* __restrict__ rsC, int rsCstride,
                             const float* __restrict__ bias, int leaky)
{
    int g = blockIdx.z;
    const float* Ag = A + (long)g * bA;
    const float* Bg = B + (long)g * bB;
    float* Cg = C + (long)g * bC;
    const float* rsAg = rsA ? rsA + (long)g * rsAstride : nullptr;
    const float* rsCg = rsC ? rsC + (long)g * rsCstride : nullptr;

    int bm = blockIdx.y * BM;
    int bn = blockIdx.x * BN;

    __shared__ __align__(16) float sA[BK][BM + 4];
    __shared__ __align__(16) float sB[BK][BN + 4];

    int tid = threadIdx.x;
    int a_row = tid >> 1;
    int a_col = (tid & 1) * 4;
    int b_row = tid >> 5;
    int b_col = (tid & 31) * 4;
    int tr = tid >> 4;
    int tc = tid & 15;

    float acc[8][8];
#pragma unroll
    for (int i = 0; i < 8; i++)
#pragma unroll
        for (int j = 0; j < 8; j++) acc[i][j] = 0.f;

    float aScale = rsAg ? rsAg[bm + a_row] : 1.f;

    for (int k0 = 0; k0 < K; k0 += BK) {
        float4 av = *(const float4*)(Ag + (long)(bm + a_row) * K + k0 + a_col);
        av.x *= aScale; av.y *= aScale; av.z *= aScale; av.w *= aScale;
        sA[a_col + 0][a_row] = av.x;
        sA[a_col + 1][a_row] = av.y;
        sA[a_col + 2][a_row] = av.z;
        sA[a_col + 3][a_row] = av.w;
        float4 bv = *(const float4*)(Bg + (long)(k0 + b_row) * N + bn + b_col);
        *(float4*)&sB[b_row][b_col] = bv;
        __syncthreads();
#pragma unroll
        for (int k = 0; k < BK; k++) {
            float4 a0 = *(const float4*)&sA[k][tr * 4];
            float4 a1 = *(const float4*)&sA[k][tr * 4 + 64];
            float4 b0 = *(const float4*)&sB[k][tc * 4];
            float4 b1 = *(const float4*)&sB[k][tc * 4 + 64];
            float ar[8] = {a0.x, a0.y, a0.z, a0.w, a1.x, a1.y, a1.z, a1.w};
            float br[8] = {b0.x, b0.y, b0.z, b0.w, b1.x, b1.y, b1.z, b1.w};
#pragma unroll
            for (int i = 0; i < 8; i++)
#pragma unroll
                for (int j = 0; j < 8; j++) acc[i][j] += ar[i] * br[j];
        }
        __syncthreads();
    }

#pragma unroll
    for (int i = 0; i < 8; i++) {
        int row = bm + ((i < 4) ? (tr * 4 + i) : (64 + tr * 4 + i - 4));
        float rs = rsCg ? rsCg[row] : 1.f;
#pragma unroll
        for (int jg = 0; jg < 2; jg++) {
            int col = bn + tc * 4 + jg * 64;
            float v[4];
#pragma unroll
            for (int jj = 0; jj < 4; jj++) {
                float c = acc[i][jg * 4 + jj] * rs;
                if (bias) c += bias[col + jj];
                if (leaky) c = (c > 0.f) ? c : 0.01f * c;
                v[jj] = c;
            }
            float4 o = make_float4(v[0], v[1], v[2], v[3]);
            *(float4*)(Cg + (long)row * N + col) = o;
        }
    }
}

// ---------------- small batched conv: X = leaky(adj@H * norm + b) ---------------
template <int NN>
__global__ void conv_small_kernel(const float* __restrict__ A, const float* __restrict__ H,
                                  const float* __restrict__ nrm, const float* __restrict__ bias,
                                  float* __restrict__ X)
{
    int g = blockIdx.x;
    __shared__ float sAdj[NN][NN + 1];
    __shared__ float sH[NN][256];
    const float* Ag = A + (long)g * NN * NN;
    const float* Hg = H + (long)g * NN * 256;
    int tid = threadIdx.x; // 256
    for (int t = tid; t < NN * NN; t += 256) sAdj[t / NN][t % NN] = Ag[t];
    for (int t = tid; t < NN * 256; t += 256) sH[t / 256][t % 256] = Hg[t];
    __syncthreads();
    int j = tid;
    float bj = bias[j];
#pragma unroll 4
    for (int i = 0; i < NN; i++) {
        float acc = 0.f;
#pragma unroll
        for (int k = 0; k < NN; k++) acc += sAdj[i][k] * sH[k][j];
        float v = acc * nrm[(long)g * NN + i] + bj;
        X[(long)g * NN * 256 + (long)i * 256 + j] = (v > 0.f) ? v : 0.01f * v;
    }
}

// ---------------- SAGPool: score -> topk -> gather/gate -> readout -> subgraph --
template <int NV, int KK>
__global__ void pool_kernel(const float* __restrict__ X, const float* __restrict__ A,
                            const float* __restrict__ nrm,
                            const float* __restrict__ Ws, const float* __restrict__ bs,
                            float* __restrict__ Xp, float* __restrict__ Aout,
                            float* __restrict__ normOut, float* __restrict__ readout,
                            int roff)
{
    int g = blockIdx.x;
    const float* Xg = X + (long)g * NV * 256;
    const float* Ag = A + (long)g * NV * NV;
    const float* ng = nrm + (long)g * NV;

    __shared__ float sWs[256];
    __shared__ float spre[NV];
    __shared__ float ssc[NV];
    __shared__ int   sidx[NV];
    __shared__ float sAn[KK * KK];

    int tid = threadIdx.x, lane = tid & 31, warp = tid >> 5;
    sWs[tid] = Ws[tid];
    __syncthreads();

    for (int r = warp; r < NV; r += 8) {
        float acc = 0.f;
        for (int q = lane; q < 256; q += 32) acc += Xg[(long)r * 256 + q] * sWs[q];
#pragma unroll
        for (int s = 16; s > 0; s >>= 1) acc += __shfl_down_sync(0xffffffffu, acc, s);
        if (lane == 0) spre[r] = ng[r] * acc;
    }
    __syncthreads();

    float bsv = bs[0];
    for (int r = warp; r < NV; r += 8) {
        float acc = 0.f;
        for (int q = lane; q < NV; q += 32) acc += Ag[(long)r * NV + q] * spre[q];
#pragma unroll
        for (int s = 16; s > 0; s >>= 1) acc += __shfl_down_sync(0xffffffffu, acc, s);
        if (lane == 0) { ssc[r] = ng[r] * acc + bsv; sidx[r] = r; }
    }
    __syncthreads();

    for (int ksz = 2; ksz <= NV; ksz <<= 1) {
        for (int j = ksz >> 1; j > 0; j >>= 1) {
            if (tid < NV) {
                int ixj = tid ^ j;
                if (ixj > tid) {
                    float s1 = ssc[tid], s2 = ssc[ixj];
                    int i1 = sidx[tid], i2 = sidx[ixj];
                    bool firstWorse = (s1 < s2) || (s1 == s2 && i1 > i2);
                    bool descRegion = ((tid & ksz) == 0);
                    bool doSwap = descRegion ? firstWorse : !firstWorse;
                    if (doSwap) {
                        ssc[tid] = s2; ssc[ixj] = s1;
                        sidx[tid] = i2; sidx[ixj] = i1;
                    }
                }
            }
            __syncthreads();
        }
    }

    if (tid < KK) ssc[tid] = tanhf(ssc[tid]);
    __syncthreads();

    {
        int j = tid;
        float csum = 0.f, cmax = -3.402823466e38f;
#pragma unroll 4
        for (int r = 0; r < KK; r++) {
            int row = sidx[r];
            float v = Xg[(long)row * 256 + j] * ssc[r];
            Xp[(long)g * KK * 256 + (long)r * 256 + j] = v;
            csum += v;
            cmax = fmaxf(cmax, v);
        }
        readout[(long)g * 1536 + roff + j] = csum;
        readout[(long)g * 1536 + roff + 256 + j] = cmax;
    }

    if (Aout) {
        for (int t = tid; t < KK * KK; t += 256) {
            int r = t / KK, c = t % KK;
            sAn[t] = Ag[(long)sidx[r] * NV + sidx[c]];
        }
        __syncthreads();
        for (int t = tid; t < KK * KK; t += 256) Aout[(long)g * KK * KK + t] = sAn[t];
        if (tid < KK) {
            float d = 0.f;
#pragma unroll
            for (int c = 0; c < KK; c++) d += sAn[tid * KK + c];
            normOut[(long)g * KK + tid] = rsqrtf(fmaxf(d, 1.f));
        }
    }
}

// ---------------- final head: out = sigmoid(h @ Wd2 + bd2) ----------------------
__global__ void head_kernel(const float* __restrict__ H, const float* __restrict__ Wd2,
                            const float* __restrict__ bd2, float* __restrict__ out)
{
    int g = blockIdx.x;
    int o = threadIdx.x >> 5;
    int lane = threadIdx.x & 31;
    float acc = 0.f;
#pragma unroll
    for (int k = lane; k < 128; k += 32) acc += H[(long)g * 128 + k] * Wd2[k * 2 + o];
#pragma unroll
    for (int s = 16; s > 0; s >>= 1) acc += __shfl_down_sync(0xffffffffu, acc, s);
    if (lane == 0) {
        float z = acc + bd2[o];
        out[g * 2 + o] = 1.f / (1.f + expf(-z));
    }
}

// --------------------------------- launch --------------------------------------
extern "C" void kernel_launch(void* const* d_in, const int* in_sizes, int n_in,
                              void* d_out, int out_size)
{
    const float* feat = (const float*)d_in[0];
    const float* adj  = (const float*)d_in[1];
    const float* W0   = (const float*)d_in[2];
    const float* b0   = (const float*)d_in[3];
    const float* Ws0  = (const float*)d_in[4];
    const float* bs0  = (const float*)d_in[5];
    const float* W1   = (const float*)d_in[6];
    const float* b1   = (const float*)d_in[7];
    const float* Ws1  = (const float*)d_in[8];
    const float* bs1  = (const float*)d_in[9];
    const float* W2   = (const float*)d_in[10];
    const float* b2   = (const float*)d_in[11];
    const float* Ws2  = (const float*)d_in[12];
    const float* bs2  = (const float*)d_in[13];
    const float* Wd1  = (const float*)d_in[14];
    const float* bd1  = (const float*)d_in[15];
    const float* Wd2  = (const float*)d_in[16];
    const float* bd2  = (const float*)d_in[17];
    float* out = (float*)d_out;

    float *p_norm0, *p_H, *p_X1, *p_Xp1, *p_A1, *p_norm1, *p_H1, *p_X2;
    float *p_Xp2, *p_A2, *p_norm2, *p_H2, *p_X3, *p_Xp3, *p_read, *p_h;
    cudaGetSymbolAddress((void**)&p_norm0, g_norm0);
    cudaGetSymbolAddress((void**)&p_H, g_H);
    cudaGetSymbolAddress((void**)&p_X1, g_X1);
    cudaGetSymbolAddress((void**)&p_Xp1, g_Xp1);
    cudaGetSymbolAddress((void**)&p_A1, g_A1);
    cudaGetSymbolAddress((void**)&p_norm1, g_norm1);
    cudaGetSymbolAddress((void**)&p_H1, g_H1);
    cudaGetSymbolAddress((void**)&p_X2, g_X2);
    cudaGetSymbolAddress((void**)&p_Xp2, g_Xp2);
    cudaGetSymbolAddress((void**)&p_A2, g_A2);
    cudaGetSymbolAddress((void**)&p_norm2, g_norm2);
    cudaGetSymbolAddress((void**)&p_H2, g_H2);
    cudaGetSymbolAddress((void**)&p_X3, g_X3);
    cudaGetSymbolAddress((void**)&p_Xp3, g_Xp3);
    cudaGetSymbolAddress((void**)&p_read, g_read);
    cudaGetSymbolAddress((void**)&p_h, g_h);

    // layer 0
    degnorm_kernel<<<G * NNODE / 8, 256>>>(adj, p_norm0);
    // H = (feat * norm0) @ W0   [tf32 split x3]
    tf32gemm_kernel<1><<<dim3(2, 2048, 1), 256>>>(feat, W0, p_H,
                                                  G * NNODE, DH, FIN, 0, 0, 0,
                                                  p_norm0, nullptr, 0, nullptr, 0);
    // X1 = leaky(adj @ H * norm0 + b0)   [adj exact, H split x2], batched
    tf32gemm_kernel<0><<<dim3(2, 2, 1024), 256>>>(adj, p_H, p_X1,
                                                  NNODE, DH, NNODE,
                                                  (long)NNODE * NNODE, (long)NNODE * DH, (long)NNODE * DH,
                                                  nullptr, p_norm0, NNODE, b0, 1);
    pool_kernel<256, 32><<<G, 256>>>(p_X1, adj, p_norm0, Ws0, bs0,
                                     p_Xp1, p_A1, p_norm1, p_read, 0);
    // layer 1
    tf32gemm_kernel<1><<<dim3(2, 256, 1), 256>>>(p_Xp1, W1, p_H1,
                                                 G * 32, DH, DH, 0, 0, 0,
                                                 p_norm1, nullptr, 0, nullptr, 0);
    conv_small_kernel<32><<<G, 256>>>(p_A1, p_H1, p_norm1, b1, p_X2);
    pool_kernel<32, 16><<<G, 256>>>(p_X2, p_A1, p_norm1, Ws1, bs1,
                                    p_Xp2, p_A2, p_norm2, p_read, 512);
    // layer 2
    tf32gemm_kernel<1><<<dim3(2, 128, 1), 256>>>(p_Xp2, W2, p_H2,
                                                 G * 16, DH, DH, 0, 0, 0,
                                                 p_norm2, nullptr, 0, nullptr, 0);
    conv_small_kernel<16><<<G, 256>>>(p_A2, p_H2, p_norm2, b2, p_X3);
    pool_kernel<16, 8><<<G, 256>>>(p_X3, p_A2, p_norm2, Ws2, bs2,
                                   p_Xp3, nullptr, nullptr, p_read, 1024);
    // MLP head
    sgemm_kernel<<<dim3(1, 8, 1), 256>>>(p_read, Wd1, p_h, G, 128, 1536,
                                         0, 0, 0, nullptr, 0, nullptr, 0, bd1, 1);
    head_kernel<<<G, 64>>>(p_h, Wd2, bd2, out);
}

// round 3
// speedup vs baseline: 1.8227x; 1.8227x over previous
#include <cuda_runtime.h>
#include <math.h>

#define G 1024
#define NNODE 256
#define FIN 128
#define DH 256
#define MAXD 128   // neighbor-list capacity (deg mean ~31, sd ~5.2; 128 is >18 sigma)

// ---------------- scratch (device globals; no allocations allowed) -------------
__device__ float g_norm0[G * NNODE];
__device__ unsigned char g_cols[(long)G * NNODE * MAXD];
__device__ int   g_cnt [G * NNODE];
__device__ float g_H  [G * NNODE * DH];
__device__ float g_X1 [G * NNODE * DH];
__device__ float g_Xp1[G * 32 * DH];
__device__ float g_A1 [G * 32 * 32];
__device__ float g_norm1[G * 32];
__device__ float g_H1 [G * 32 * DH];
__device__ float g_X2 [G * 32 * DH];
__device__ float g_Xp2[G * 16 * DH];
__device__ float g_A2 [G * 16 * 16];
__device__ float g_norm2[G * 16];
__device__ float g_H2 [G * 16 * DH];
__device__ float g_X3 [G * 16 * DH];
__device__ float g_Xp3[G * 8 * DH];
__device__ float g_read[G * 1536];
__device__ float g_h  [G * 128];

// ---------------- f32x2 helpers -------------------------------------------------
#define FFMA2(acc, a, b) asm("fma.rn.f32x2 %0, %1, %2, %0;" : "+l"(acc) : "l"(a), "l"(b))
#define FADD2(acc, h)    asm("add.rn.f32x2 %0, %0, %1;"     : "+l"(acc) : "l"(h))

static __device__ __forceinline__ unsigned long long bcast2(float x) {
    unsigned long long r; unsigned u = __float_as_uint(x);
    asm("mov.b64 %0, {%1, %1};" : "=l"(r) : "r"(u));
    return r;
}
static __device__ __forceinline__ float2 unpack2(unsigned long long v) {
    unsigned lo, hi;
    asm("mov.b64 {%0, %1}, %2;" : "=r"(lo), "=r"(hi) : "l"(v));
    return make_float2(__uint_as_float(lo), __uint_as_float(hi));
}

// ---------------- build sparse adjacency lists + degree norm -------------------
// one warp per row; ballot/popc stream compaction; adjacency entries are exactly
// 0.0f / 1.0f so count == degree sum.
__global__ void build_adj_kernel(const float* __restrict__ adj,
                                 unsigned char* __restrict__ cols,
                                 int* __restrict__ cnt, float* __restrict__ nrm)
{
    int row  = blockIdx.x * 8 + (threadIdx.x >> 5);
    int lane = threadIdx.x & 31;
    const float* a = adj + (long)row * 256;
    unsigned char* lst = cols + (long)row * MAXD;
    int base = 0;
#pragma unroll
    for (int c = 0; c < 8; c++) {
        float v = a[c * 32 + lane];
        unsigned m = __ballot_sync(0xffffffffu, v != 0.f);
        if (v != 0.f) {
            int pos = base + __popc(m & ((1u << lane) - 1));
            if (pos < MAXD) lst[pos] = (unsigned char)(c * 32 + lane);
        }
        base += __popc(m);
    }
    if (lane == 0) {
        cnt[row] = (base > MAXD) ? MAXD : base;
        nrm[row] = rsqrtf(fmaxf((float)base, 1.f));
    }
}

// ---------------- sparse SpMM: X1 = leaky(norm .* (adj @ H) + b) ----------------
// grid (2 col-chunks, G graphs), 256 threads, 128KB dynamic smem for H chunk.
__global__ void spmm_kernel(const unsigned char* __restrict__ cols,
                            const int* __restrict__ cnt,
                            const float* __restrict__ H,
                            const float* __restrict__ nrm,
                            const float* __restrict__ bias,
                            float* __restrict__ X1)
{
    extern __shared__ float sH[];                 // [256][128]
    __shared__ unsigned char sCols[256 * MAXD];   // 32 KB
    __shared__ int   scnt[256];
    __shared__ float snrm[256];

    int g = blockIdx.y, chunk = blockIdx.x;
    int tid = threadIdx.x;

    // load H chunk [256 rows x 128 cols]
    {
        const float4* Hg = (const float4*)(H + (long)g * 65536 + chunk * 128);
        float4* s4 = (float4*)sH;
        for (int t = tid; t < 8192; t += 256) {
            int r = t >> 5, c4 = t & 31;
            s4[r * 32 + c4] = Hg[(long)r * 64 + c4];
        }
    }
    // load neighbor lists + counts + norms
    {
        const uint4* gc = (const uint4*)(cols + (long)g * 256 * MAXD);
        uint4* sc = (uint4*)sCols;
        for (int t = tid; t < 2048; t += 256) sc[t] = gc[t];
        scnt[tid] = cnt[g * 256 + tid];
        snrm[tid] = nrm[g * 256 + tid];
    }
    __syncthreads();

    int col4 = tid & 31;     // which float4 of the 128-col chunk
    int rg   = tid >> 5;     // row group (8 rows in flight)
    float4 bcol = *(const float4*)&bias[chunk * 128 + col4 * 4];

    for (int i = rg; i < 256; i += 8) {
        int d = scnt[i];
        const unsigned char* lst = &sCols[i * MAXD];
        unsigned long long acc0 = 0ull, acc1 = 0ull;
        int k = 0;
        for (; k + 4 <= d; k += 4) {
            unsigned w = *(const unsigned*)(lst + k);
            int j0 = w & 255, j1 = (w >> 8) & 255, j2 = (w >> 16) & 255, j3 = w >> 24;
            ulonglong2 h0 = *(const ulonglong2*)(sH + j0 * 128 + col4 * 4);
            ulonglong2 h1 = *(const ulonglong2*)(sH + j1 * 128 + col4 * 4);
            ulonglong2 h2 = *(const ulonglong2*)(sH + j2 * 128 + col4 * 4);
            ulonglong2 h3 = *(const ulonglong2*)(sH + j3 * 128 + col4 * 4);
            FADD2(acc0, h0.x); FADD2(acc1, h0.y);
            FADD2(acc0, h1.x); FADD2(acc1, h1.y);
            FADD2(acc0, h2.x); FADD2(acc1, h2.y);
            FADD2(acc0, h3.x); FADD2(acc1, h3.y);
        }
        for (; k < d; k++) {
            int j = lst[k];
            ulonglong2 h = *(const ulonglong2*)(sH + j * 128 + col4 * 4);
            FADD2(acc0, h.x); FADD2(acc1, h.y);
        }
        float2 p0 = unpack2(acc0), p1 = unpack2(acc1);
        float nr = snrm[i];
        float v0 = p0.x * nr + bcol.x;
        float v1 = p0.y * nr + bcol.y;
        float v2 = p1.x * nr + bcol.z;
        float v3 = p1.y * nr + bcol.w;
        v0 = (v0 > 0.f) ? v0 : 0.01f * v0;
        v1 = (v1 > 0.f) ? v1 : 0.01f * v1;
        v2 = (v2 > 0.f) ? v2 : 0.01f * v2;
        v3 = (v3 > 0.f) ? v3 : 0.01f * v3;
        *(float4*)(X1 + (long)g * 65536 + (long)i * 256 + chunk * 128 + col4 * 4) =
            make_float4(v0, v1, v2, v3);
    }
}

// ---------------- dense SGEMM with packed f32x2 FFMA ---------------------------
// C[g] = epilogue( (rowscaleA .* A[g]) @ B[g] );  BM=BN=128, BK=8, 256 threads.
#define BM 128
#define BN 128
#define BK 8

__global__ void sgemm_kernel(const float* __restrict__ A, const float* __restrict__ B,
                             float* __restrict__ C,
                             int M, int N, int K,
                             long bA, long bB, long bC,
                             const float* __restrict__ rsA, int rsAstride,
                             const float* __restrict__ rsC, int rsCstride,
                             const float* __restrict__ bias, int leaky)
{
    int g = blockIdx.z;
    const float* Ag = A + (long)g * bA;
    const float* Bg = B + (long)g * bB;
    float* Cg = C + (long)g * bC;
    const float* rsAg = rsA ? rsA + (long)g * rsAstride : nullptr;
    const float* rsCg = rsC ? rsC + (long)g * rsCstride : nullptr;

    int bm = blockIdx.y * BM;
    int bn = blockIdx.x * BN;

    __shared__ __align__(16) float sA[BK][BM + 4];
    __shared__ __align__(16) float sB[BK][BN + 4];

    int tid = threadIdx.x;
    int a_row = tid >> 1;
    int a_col = (tid & 1) * 4;
    int b_row = tid >> 5;
    int b_col = (tid & 31) * 4;
    int tr = tid >> 4;
    int tc = tid & 15;

    // packed accumulators: accp[p][j] = (acc[2p][j], acc[2p+1][j]) over M-pairs
    unsigned long long accp[4][8];
#pragma unroll
    for (int p = 0; p < 4; p++)
#pragma unroll
        for (int j = 0; j < 8; j++) accp[p][j] = 0ull;

    float aScale = rsAg ? rsAg[bm + a_row] : 1.f;

    for (int k0 = 0; k0 < K; k0 += BK) {
        float4 av = *(const float4*)(Ag + (long)(bm + a_row) * K + k0 + a_col);
        av.x *= aScale; av.y *= aScale; av.z *= aScale; av.w *= aScale;
        sA[a_col + 0][a_row] = av.x;
        sA[a_col + 1][a_row] = av.y;
        sA[a_col + 2][a_row] = av.z;
        sA[a_col + 3][a_row] = av.w;
        float4 bv = *(const float4*)(Bg + (long)(k0 + b_row) * N + bn + b_col);
        *(float4*)&sB[b_row][b_col] = bv;
        __syncthreads();
#pragma unroll
        for (int k = 0; k < BK; k++) {
            ulonglong2 ap0 = *(const ulonglong2*)&sA[k][tr * 4];
            ulonglong2 ap1 = *(const ulonglong2*)&sA[k][tr * 4 + 64];
            float4 b0 = *(const float4*)&sB[k][tc * 4];
            float4 b1 = *(const float4*)&sB[k][tc * 4 + 64];
            unsigned long long ap[4] = {ap0.x, ap0.y, ap1.x, ap1.y};
            unsigned long long bb[8] = {bcast2(b0.x), bcast2(b0.y), bcast2(b0.z), bcast2(b0.w),
                                        bcast2(b1.x), bcast2(b1.y), bcast2(b1.z), bcast2(b1.w)};
#pragma unroll
            for (int j = 0; j < 8; j++)
#pragma unroll
                for (int p = 0; p < 4; p++) FFMA2(accp[p][j], ap[p], bb[j]);
        }
        __syncthreads();
    }

#pragma unroll
    for (int p = 0; p < 4; p++) {
        int rowbase = bm + ((p < 2) ? (tr * 4 + 2 * p) : (64 + tr * 4 + 2 * (p - 2)));
        float rs0 = rsCg ? rsCg[rowbase] : 1.f;
        float rs1 = rsCg ? rsCg[rowbase + 1] : 1.f;
#pragma unroll
        for (int jg = 0; jg < 2; jg++) {
            int col = bn + tc * 4 + jg * 64;
            float vlo[4], vhi[4];
#pragma unroll
            for (int jj = 0; jj < 4; jj++) {
                float2 pr = unpack2(accp[p][jg * 4 + jj]);
                float c0 = pr.x * rs0;
                float c1 = pr.y * rs1;
                if (bias) { float bv = bias[col + jj]; c0 += bv; c1 += bv; }
                if (leaky) {
                    c0 = (c0 > 0.f) ? c0 : 0.01f * c0;
                    c1 = (c1 > 0.f) ? c1 : 0.01f * c1;
                }
                vlo[jj] = c0; vhi[jj] = c1;
            }
            *(float4*)(Cg + (long)rowbase * N + col) = make_float4(vlo[0], vlo[1], vlo[2], vlo[3]);
            *(float4*)(Cg + (long)(rowbase + 1) * N + col) = make_float4(vhi[0], vhi[1], vhi[2], vhi[3]);
        }
    }
}

// ---------------- small batched conv: X = leaky(adj@H * norm + b) ---------------
template <int NN>
__global__ void conv_small_kernel(const float* __restrict__ A, const float* __restrict__ H,
                                  const float* __restrict__ nrm, const float* __restrict__ bias,
                                  float* __restrict__ X)
{
    int g = blockIdx.x;
    __shared__ float sAdj[NN][NN + 1];
    __shared__ float sH[NN][256];
    const float* Ag = A + (long)g * NN * NN;
    const float* Hg = H + (long)g * NN * 256;
    int tid = threadIdx.x;
    for (int t = tid; t < NN * NN; t += 256) sAdj[t / NN][t % NN] = Ag[t];
    for (int t = tid; t < NN * 256; t += 256) sH[t / 256][t % 256] = Hg[t];
    __syncthreads();
    int j = tid;
    float bj = bias[j];
#pragma unroll 4
    for (int i = 0; i < NN; i++) {
        float acc = 0.f;
#pragma unroll
        for (int k = 0; k < NN; k++) acc += sAdj[i][k] * sH[k][j];
        float v = acc * nrm[(long)g * NN + i] + bj;
        X[(long)g * NN * 256 + (long)i * 256 + j] = (v > 0.f) ? v : 0.01f * v;
    }
}

// ---------------- SAGPool: score -> topk -> gather/gate -> readout -> subgraph --
// colsL/cntL non-null (layer 0): sparse score aggregation; else dense rows of A.
template <int NV, int KK>
__global__ void pool_kernel(const float* __restrict__ X, const float* __restrict__ A,
                            const float* __restrict__ nrm,
                            const float* __restrict__ Ws, const float* __restrict__ bs,
                            const unsigned char* __restrict__ colsL,
                            const int* __restrict__ cntL,
                            float* __restrict__ Xp, float* __restrict__ Aout,
                            float* __restrict__ normOut, float* __restrict__ readout,
                            int roff)
{
    int g = blockIdx.x;
    const float* Xg = X + (long)g * NV * 256;
    const float* Ag = A + (long)g * NV * NV;
    const float* ng = nrm + (long)g * NV;

    __shared__ float sWs[256];
    __shared__ float spre[NV];
    __shared__ float ssc[NV];
    __shared__ int   sidx[NV];
    __shared__ float sAn[KK * KK];

    int tid = threadIdx.x, lane = tid & 31, warp = tid >> 5;
    sWs[tid] = Ws[tid];
    __syncthreads();

    for (int r = warp; r < NV; r += 8) {
        float acc = 0.f;
        for (int q = lane; q < 256; q += 32) acc += Xg[(long)r * 256 + q] * sWs[q];
#pragma unroll
        for (int s = 16; s > 0; s >>= 1) acc += __shfl_down_sync(0xffffffffu, acc, s);
        if (lane == 0) spre[r] = ng[r] * acc;
    }
    __syncthreads();

    float bsv = bs[0];
    if (colsL) {
        for (int r = warp; r < NV; r += 8) {
            int d = cntL[g * NV + r];
            const unsigned char* lst = colsL + ((long)g * NV + r) * MAXD;
            float acc = 0.f;
            for (int q = lane; q < d; q += 32) acc += spre[lst[q]];
#pragma unroll
            for (int s = 16; s > 0; s >>= 1) acc += __shfl_down_sync(0xffffffffu, acc, s);
            if (lane == 0) { ssc[r] = ng[r] * acc + bsv; sidx[r] = r; }
        }
    } else {
        for (int r = warp; r < NV; r += 8) {
            float acc = 0.f;
            for (int q = lane; q < NV; q += 32) acc += Ag[(long)r * NV + q] * spre[q];
#pragma unroll
            for (int s = 16; s > 0; s >>= 1) acc += __shfl_down_sync(0xffffffffu, acc, s);
            if (lane == 0) { ssc[r] = ng[r] * acc + bsv; sidx[r] = r; }
        }
    }
    __syncthreads();

    // bitonic sort, descending, ties -> lower index
    for (int ksz = 2; ksz <= NV; ksz <<= 1) {
        for (int j = ksz >> 1; j > 0; j >>= 1) {
            if (tid < NV) {
                int ixj = tid ^ j;
                if (ixj > tid) {
                    float s1 = ssc[tid], s2 = ssc[ixj];
                    int i1 = sidx[tid], i2 = sidx[ixj];
                    bool firstWorse = (s1 < s2) || (s1 == s2 && i1 > i2);
                    bool descRegion = ((tid & ksz) == 0);
                    bool doSwap = descRegion ? firstWorse : !firstWorse;
                    if (doSwap) {
                        ssc[tid] = s2; ssc[ixj] = s1;
                        sidx[tid] = i2; sidx[ixj] = i1;
                    }
                }
            }
            __syncthreads();
        }
    }

    if (tid < KK) ssc[tid] = tanhf(ssc[tid]);
    __syncthreads();

    {
        int j = tid;
        float csum = 0.f, cmax = -3.402823466e38f;
#pragma unroll 4
        for (int r = 0; r < KK; r++) {
            int row = sidx[r];
            float v = Xg[(long)row * 256 + j] * ssc[r];
            Xp[(long)g * KK * 256 + (long)r * 256 + j] = v;
            csum += v;
            cmax = fmaxf(cmax, v);
        }
        readout[(long)g * 1536 + roff + j] = csum;
        readout[(long)g * 1536 + roff + 256 + j] = cmax;
    }

    if (Aout) {
        for (int t = tid; t < KK * KK; t += 256) {
            int r = t / KK, c = t % KK;
            sAn[t] = Ag[(long)sidx[r] * NV + sidx[c]];
        }
        __syncthreads();
        for (int t = tid; t < KK * KK; t += 256) Aout[(long)g * KK * KK + t] = sAn[t];
        if (tid < KK) {
            float d = 0.f;
#pragma unroll
            for (int c = 0; c < KK; c++) d += sAn[tid * KK + c];
            normOut[(long)g * KK + tid] = rsqrtf(fmaxf(d, 1.f));
        }
    }
}

// ---------------- final head: out = sigmoid(h @ Wd2 + bd2) ----------------------
__global__ void head_kernel(const float* __restrict__ H, const float* __restrict__ Wd2,
                            const float* __restrict__ bd2, float* __restrict__ out)
{
    int g = blockIdx.x;
    int o = threadIdx.x >> 5;
    int lane = threadIdx.x & 31;
    float acc = 0.f;
#pragma unroll
    for (int k = lane; k < 128; k += 32) acc += H[(long)g * 128 + k] * Wd2[k * 2 + o];
#pragma unroll
    for (int s = 16; s > 0; s >>= 1) acc += __shfl_down_sync(0xffffffffu, acc, s);
    if (lane == 0) {
        float z = acc + bd2[o];
        out[g * 2 + o] = 1.f / (1.f + expf(-z));
    }
}

// --------------------------------- launch --------------------------------------
extern "C" void kernel_launch(void* const* d_in, const int* in_sizes, int n_in,
                              void* d_out, int out_size)
{
    const float* feat = (const float*)d_in[0];
    const float* adj  = (const float*)d_in[1];
    const float* W0   = (const float*)d_in[2];
    const float* b0   = (const float*)d_in[3];
    const float* Ws0  = (const float*)d_in[4];
    const float* bs0  = (const float*)d_in[5];
    const float* W1   = (const float*)d_in[6];
    const float* b1   = (const float*)d_in[7];
    const float* Ws1  = (const float*)d_in[8];
    const float* bs1  = (const float*)d_in[9];
    const float* W2   = (const float*)d_in[10];
    const float* b2   = (const float*)d_in[11];
    const float* Ws2  = (const float*)d_in[12];
    const float* bs2  = (const float*)d_in[13];
    const float* Wd1  = (const float*)d_in[14];
    const float* bd1  = (const float*)d_in[15];
    const float* Wd2  = (const float*)d_in[16];
    const float* bd2  = (const float*)d_in[17];
    float* out = (float*)d_out;

    float *p_norm0, *p_H, *p_X1, *p_Xp1, *p_A1, *p_norm1, *p_H1, *p_X2;
    float *p_Xp2, *p_A2, *p_norm2, *p_H2, *p_X3, *p_Xp3, *p_read, *p_h;
    unsigned char* p_cols; int* p_cnt;
    cudaGetSymbolAddress((void**)&p_norm0, g_norm0);
    cudaGetSymbolAddress((void**)&p_cols, g_cols);
    cudaGetSymbolAddress((void**)&p_cnt, g_cnt);
    cudaGetSymbolAddress((void**)&p_H, g_H);
    cudaGetSymbolAddress((void**)&p_X1, g_X1);
    cudaGetSymbolAddress((void**)&p_Xp1, g_Xp1);
    cudaGetSymbolAddress((void**)&p_A1, g_A1);
    cudaGetSymbolAddress((void**)&p_norm1, g_norm1);
    cudaGetSymbolAddress((void**)&p_H1, g_H1);
    cudaGetSymbolAddress((void**)&p_X2, g_X2);
    cudaGetSymbolAddress((void**)&p_Xp2, g_Xp2);
    cudaGetSymbolAddress((void**)&p_A2, g_A2);
    cudaGetSymbolAddress((void**)&p_norm2, g_norm2);
    cudaGetSymbolAddress((void**)&p_H2, g_H2);
    cudaGetSymbolAddress((void**)&p_X3, g_X3);
    cudaGetSymbolAddress((void**)&p_Xp3, g_Xp3);
    cudaGetSymbolAddress((void**)&p_read, g_read);
    cudaGetSymbolAddress((void**)&p_h, g_h);

    cudaFuncSetAttribute(spmm_kernel, cudaFuncAttributeMaxDynamicSharedMemorySize, 131072);

    // layer 0
    build_adj_kernel<<<G * NNODE / 8, 256>>>(adj, p_cols, p_cnt, p_norm0);
    sgemm_kernel<<<dim3(2, 2048, 1), 256>>>(feat, W0, p_H, G * NNODE, DH, FIN,
                                            0, 0, 0, p_norm0, 0, nullptr, 0, nullptr, 0);
    spmm_kernel<<<dim3(2, G, 1), 256, 131072>>>(p_cols, p_cnt, p_H, p_norm0, b0, p_X1);
    pool_kernel<256, 32><<<G, 256>>>(p_X1, adj, p_norm0, Ws0, bs0, p_cols, p_cnt,
                                     p_Xp1, p_A1, p_norm1, p_read, 0);
    // layer 1
    sgemm_kernel<<<dim3(2, 256, 1), 256>>>(p_Xp1, W1, p_H1, G * 32, DH, DH,
                                           0, 0, 0, p_norm1, 0, nullptr, 0, nullptr, 0);
    conv_small_kernel<32><<<G, 256>>>(p_A1, p_H1, p_norm1, b1, p_X2);
    pool_kernel<32, 16><<<G, 256>>>(p_X2, p_A1, p_norm1, Ws1, bs1, nullptr, nullptr,
                                    p_Xp2, p_A2, p_norm2, p_read, 512);
    // layer 2
    sgemm_kernel<<<dim3(2, 128, 1), 256>>>(p_Xp2, W2, p_H2, G * 16, DH, DH,
                                           0, 0, 0, p_norm2, 0, nullptr, 0, nullptr, 0);
    conv_small_kernel<16><<<G, 256>>>(p_A2, p_H2, p_norm2, b2, p_X3);
    pool_kernel<16, 8><<<G, 256>>>(p_X3, p_A2, p_norm2, Ws2, bs2, nullptr, nullptr,
                                   p_Xp3, nullptr, nullptr, p_read, 1024);
    // MLP head
    sgemm_kernel<<<dim3(1, 8, 1), 256>>>(p_read, Wd1, p_h, G, 128, 1536,
                                         0, 0, 0, nullptr, 0, nullptr, 0, bd1, 1);
    head_kernel<<<G, 64>>>(p_h, Wd2, bd2, out);
}

// round 5
// speedup vs baseline: 2.1088x; 1.1570x over previous
#include <cuda_runtime.h>
#include <math.h>

#define G 1024
#define NNODE 256
#define FIN 128
#define DH 256
#define MAXD 128

// ---------------- scratch (device globals; no allocations allowed) -------------
__device__ float g_norm0[G * NNODE];
__device__ unsigned char g_cols[(long)G * NNODE * MAXD];
__device__ int   g_cnt [G * NNODE];
__device__ float g_Y  [G * NNODE * FIN];    // norm.*(A@(norm.*x))
__device__ float g_X1 [G * NNODE * DH];
__device__ float g_spre[2 * G * NNODE];     // partial X1·Ws0 dots (one per bn block)
__device__ float g_Xp1[G * 32 * DH];
__device__ float g_A1 [G * 32 * 32];
__device__ float g_norm1[G * 32];
__device__ float g_H1 [G * 32 * DH];
__device__ float g_X2 [G * 32 * DH];
__device__ float g_Xp2[G * 16 * DH];
__device__ float g_A2 [G * 16 * 16];
__device__ float g_norm2[G * 16];
__device__ float g_H2 [G * 16 * DH];
__device__ float g_X3 [G * 16 * DH];
__device__ float g_Xp3[G * 8 * DH];
__device__ float g_read[G * 1536];
__device__ float g_h  [G * 128];

// ---------------- build sparse adjacency lists + degree norm -------------------
__global__ void build_adj_kernel(const float* __restrict__ adj,
                                 unsigned char* __restrict__ cols,
                                 int* __restrict__ cnt, float* __restrict__ nrm)
{
    int row  = blockIdx.x * 8 + (threadIdx.x >> 5);
    int lane = threadIdx.x & 31;
    const float* a = adj + (long)row * 256;
    unsigned char* lst = cols + (long)row * MAXD;
    int base = 0;
#pragma unroll
    for (int c = 0; c < 8; c++) {
        float v = a[c * 32 + lane];
        unsigned m = __ballot_sync(0xffffffffu, v != 0.f);
        if (v != 0.f) {
            int pos = base + __popc(m & ((1u << lane) - 1));
            if (pos < MAXD) lst[pos] = (unsigned char)(c * 32 + lane);
        }
        base += __popc(m);
    }
    if (lane == 0) {
        cnt[row] = (base > MAXD) ? MAXD : base;
        nrm[row] = rsqrtf(fmaxf((float)base, 1.f));
    }
}

// ------- layer-0 sparse aggregation in INPUT space (128 cols): ------------------
// Y[g,i,:] = norm[i] * sum_{j in N(i)} norm[j] * x[g,j,:]
__global__ void spmm_feat_kernel(const unsigned char* __restrict__ cols,
                                 const int* __restrict__ cnt,
                                 const float* __restrict__ feat,
                                 const float* __restrict__ nrm,
                                 float* __restrict__ Y)
{
    extern __shared__ float sX[];                 // [256][128] = 128 KB
    __shared__ unsigned char sCols[256 * MAXD];   // 32 KB
    __shared__ int   scnt[256];
    __shared__ float snrm[256];

    int g = blockIdx.x, tid = threadIdx.x;
    scnt[tid] = cnt[g * 256 + tid];
    snrm[tid] = nrm[g * 256 + tid];
    __syncthreads();

    {
        const float4* Xg = (const float4*)(feat + (long)g * 32768);
        float4* s4 = (float4*)sX;
        for (int t = tid; t < 8192; t += 256) {
            int r = t >> 5;
            float4 v = Xg[t];
            float s = snrm[r];
            v.x *= s; v.y *= s; v.z *= s; v.w *= s;
            s4[t] = v;
        }
        const uint4* gc = (const uint4*)(cols + (long)g * 256 * MAXD);
        uint4* sc = (uint4*)sCols;
        for (int t = tid; t < 2048; t += 256) sc[t] = gc[t];
    }
    __syncthreads();

    int col4 = tid & 31;      // float4 index within 128 cols
    int rg   = tid >> 5;
    for (int i = rg; i < 256; i += 8) {
        int d = scnt[i];
        const unsigned char* lst = &sCols[i * MAXD];
        float a0 = 0.f, a1 = 0.f, a2 = 0.f, a3 = 0.f;
        int k = 0;
        for (; k + 4 <= d; k += 4) {
            unsigned w = *(const unsigned*)(lst + k);
            int j0 = w & 255, j1 = (w >> 8) & 255, j2 = (w >> 16) & 255, j3 = w >> 24;
            float4 h0 = *(const float4*)(sX + j0 * 128 + col4 * 4);
            float4 h1 = *(const float4*)(sX + j1 * 128 + col4 * 4);
            float4 h2 = *(const float4*)(sX + j2 * 128 + col4 * 4);
            float4 h3 = *(const float4*)(sX + j3 * 128 + col4 * 4);
            a0 += h0.x + h1.x + h2.x + h3.x;
            a1 += h0.y + h1.y + h2.y + h3.y;
            a2 += h0.z + h1.z + h2.z + h3.z;
            a3 += h0.w + h1.w + h2.w + h3.w;
        }
        for (; k < d; k++) {
            int j = lst[k];
            float4 h = *(const float4*)(sX + j * 128 + col4 * 4);
            a0 += h.x; a1 += h.y; a2 += h.z; a3 += h.w;
        }
        float nr = snrm[i];
        *(float4*)(Y + (long)g * 32768 + (long)i * 128 + col4 * 4) =
            make_float4(a0 * nr, a1 * nr, a2 * nr, a3 * nr);
    }
}

// ---------------- dense scalar SGEMM (round-1 proven) + optional fused dot -----
// C[g] = epilogue( (rowscaleA .* A[g]) @ B[g] )
// If Wsp != null: spreOut[blockIdx.x * M + row] = sum_col C[row,col]*Wsp[bn+col]
// (partial over this block's 128-col slice; deterministic shuffle reduction).
#define BM 128
#define BN 128
#define BK 8

__global__ void sgemm_kernel(const float* __restrict__ A, const float* __restrict__ B,
                             float* __restrict__ C,
                             int M, int N, int K,
                             long bA, long bB, long bC,
                             const float* __restrict__ rsA, int rsAstride,
                             const float* __restrict__ rsC, int rsCstride,
                             const float* __restrict__ bias, int leaky,
                             const float* __restrict__ Wsp, float* __restrict__ spreOut)
{
    int g = blockIdx.z;
    const float* Ag = A + (long)g * bA;
    const float* Bg = B + (long)g * bB;
    float* Cg = C + (long)g * bC;
    const float* rsAg = rsA ? rsA + (long)g * rsAstride : nullptr;
    const float* rsCg = rsC ? rsC + (long)g * rsCstride : nullptr;

    int bm = blockIdx.y * BM;
    int bn = blockIdx.x * BN;

    __shared__ __align__(16) float sA[BK][BM + 4];
    __shared__ __align__(16) float sB[BK][BN + 4];

    int tid = threadIdx.x;
    int a_row = tid >> 1;
    int a_col = (tid & 1) * 4;
    int b_row = tid >> 5;
    int b_col = (tid & 31) * 4;
    int tr = tid >> 4;
    int tc = tid & 15;

    float acc[8][8];
#pragma unroll
    for (int i = 0; i < 8; i++)
#pragma unroll
        for (int j = 0; j < 8; j++) acc[i][j] = 0.f;

    float aScale = rsAg ? rsAg[bm + a_row] : 1.f;

    for (int k0 = 0; k0 < K; k0 += BK) {
        float4 av = *(const float4*)(Ag + (long)(bm + a_row) * K + k0 + a_col);
        av.x *= aScale; av.y *= aScale; av.z *= aScale; av.w *= aScale;
        sA[a_col + 0][a_row] = av.x;
        sA[a_col + 1][a_row] = av.y;
        sA[a_col + 2][a_row] = av.z;
        sA[a_col + 3][a_row] = av.w;
        float4 bv = *(const float4*)(Bg + (long)(k0 + b_row) * N + bn + b_col);
        *(float4*)&sB[b_row][b_col] = bv;
        __syncthreads();
#pragma unroll
        for (int k = 0; k < BK; k++) {
            float4 a0 = *(const float4*)&sA[k][tr * 4];
            float4 a1 = *(const float4*)&sA[k][tr * 4 + 64];
            float4 b0 = *(const float4*)&sB[k][tc * 4];
            float4 b1 = *(const float4*)&sB[k][tc * 4 + 64];
            float ar[8] = {a0.x, a0.y, a0.z, a0.w, a1.x, a1.y, a1.z, a1.w};
            float br[8] = {b0.x, b0.y, b0.z, b0.w, b1.x, b1.y, b1.z, b1.w};
#pragma unroll
            for (int i = 0; i < 8; i++)
#pragma unroll
                for (int j = 0; j < 8; j++) acc[i][j] += ar[i] * br[j];
        }
        __syncthreads();
    }

#pragma unroll
    for (int i = 0; i < 8; i++) {
        int row = bm + ((i < 4) ? (tr * 4 + i) : (64 + tr * 4 + i - 4));
        float rs = rsCg ? rsCg[row] : 1.f;
        float rd = 0.f;
#pragma unroll
        for (int jg = 0; jg < 2; jg++) {
            int col = bn + tc * 4 + jg * 64;
            float v[4];
#pragma unroll
            for (int jj = 0; jj < 4; jj++) {
                float c = acc[i][jg * 4 + jj] * rs;
                if (bias) c += bias[col + jj];
                if (leaky) c = (c > 0.f) ? c : 0.01f * c;
                v[jj] = c;
                if (Wsp) rd += c * __ldg(&Wsp[col + jj]);
            }
            float4 o = make_float4(v[0], v[1], v[2], v[3]);
            *(float4*)(Cg + (long)row * N + col) = o;
        }
        if (Wsp) {
            // reduce rd across the 16 threads (tc=0..15) sharing this row;
            // they are consecutive lanes within a warp -> deterministic.
#pragma unroll
            for (int s = 8; s > 0; s >>= 1)
                rd += __shfl_xor_sync(0xffffffffu, rd, s);
            if (tc == 0) spreOut[(long)blockIdx.x * M + row] = rd;
        }
    }
}

// ---------------- small batched conv: X = leaky(adj@H * norm + b) ---------------
template <int NN>
__global__ void conv_small_kernel(const float* __restrict__ A, const float* __restrict__ H,
                                  const float* __restrict__ nrm, const float* __restrict__ bias,
                                  float* __restrict__ X)
{
    int g = blockIdx.x;
    __shared__ float sAdj[NN][NN + 1];
    __shared__ float sH[NN][256];
    const float* Ag = A + (long)g * NN * NN;
    const float* Hg = H + (long)g * NN * 256;
    int tid = threadIdx.x;
    for (int t = tid; t < NN * NN; t += 256) sAdj[t / NN][t % NN] = Ag[t];
    for (int t = tid; t < NN * 256; t += 256) sH[t / 256][t % 256] = Hg[t];
    __syncthreads();
    int j = tid;
    float bj = bias[j];
#pragma unroll 4
    for (int i = 0; i < NN; i++) {
        float acc = 0.f;
#pragma unroll
        for (int k = 0; k < NN; k++) acc += sAdj[i][k] * sH[k][j];
        float v = acc * nrm[(long)g * NN + i] + bj;
        X[(long)g * NN * 256 + (long)i * 256 + j] = (v > 0.f) ? v : 0.01f * v;
    }
}

// ---------------- SAGPool ------------------------------------------------------
// spreParts non-null (layer 0): pre-dot comes fused from the GEMM (2 partials).
// colsL non-null (layer 0): sparse neighbor-sum for scores.
template <int NV, int KK>
__global__ void pool_kernel(const float* __restrict__ X, const float* __restrict__ A,
                            const float* __restrict__ nrm,
                            const float* __restrict__ Ws, const float* __restrict__ bs,
                            const unsigned char* __restrict__ colsL,
                            const int* __restrict__ cntL,
                            const float* __restrict__ spreParts,
                            float* __restrict__ Xp, float* __restrict__ Aout,
                            float* __restrict__ normOut, float* __restrict__ readout,
                            int roff)
{
    int g = blockIdx.x;
    const float* Xg = X + (long)g * NV * 256;
    const float* Ag = A + (long)g * NV * NV;
    const float* ng = nrm + (long)g * NV;

    __shared__ float sWs[256];
    __shared__ float spre[NV];
    __shared__ float ssc[NV];
    __shared__ int   sidx[NV];
    __shared__ float sAn[KK * KK];

    int tid = threadIdx.x, lane = tid & 31, warp = tid >> 5;

    if (spreParts) {
        if (tid < NV)
            spre[tid] = (spreParts[(long)g * NV + tid] +
                         spreParts[(long)G * NNODE + (long)g * NV + tid]) * ng[tid];
        __syncthreads();
    } else {
        sWs[tid] = Ws[tid];
        __syncthreads();
        for (int r = warp; r < NV; r += 8) {
            float acc = 0.f;
            for (int q = lane; q < 256; q += 32) acc += Xg[(long)r * 256 + q] * sWs[q];
#pragma unroll
            for (int s = 16; s > 0; s >>= 1) acc += __shfl_down_sync(0xffffffffu, acc, s);
            if (lane == 0) spre[r] = ng[r] * acc;
        }
        __syncthreads();
    }

    float bsv = bs[0];
    if (colsL) {
        for (int r = warp; r < NV; r += 8) {
            int d = cntL[g * NV + r];
            const unsigned char* lst = colsL + ((long)g * NV + r) * MAXD;
            float acc = 0.f;
            for (int q = lane; q < d; q += 32) acc += spre[lst[q]];
#pragma unroll
            for (int s = 16; s > 0; s >>= 1) acc += __shfl_down_sync(0xffffffffu, acc, s);
            if (lane == 0) { ssc[r] = ng[r] * acc + bsv; sidx[r] = r; }
        }
    } else {
        for (int r = warp; r < NV; r += 8) {
            float acc = 0.f;
            for (int q = lane; q < NV; q += 32) acc += Ag[(long)r * NV + q] * spre[q];
#pragma unroll
            for (int s = 16; s > 0; s >>= 1) acc += __shfl_down_sync(0xffffffffu, acc, s);
            if (lane == 0) { ssc[r] = ng[r] * acc + bsv; sidx[r] = r; }
        }
    }
    __syncthreads();

    for (int ksz = 2; ksz <= NV; ksz <<= 1) {
        for (int j = ksz >> 1; j > 0; j >>= 1) {
            if (tid < NV) {
                int ixj = tid ^ j;
                if (ixj > tid) {
                    float s1 = ssc[tid], s2 = ssc[ixj];
                    int i1 = sidx[tid], i2 = sidx[ixj];
                    bool firstWorse = (s1 < s2) || (s1 == s2 && i1 > i2);
                    bool descRegion = ((tid & ksz) == 0);
                    bool doSwap = descRegion ? firstWorse : !firstWorse;
                    if (doSwap) {
                        ssc[tid] = s2; ssc[ixj] = s1;
                        sidx[tid] = i2; sidx[ixj] = i1;
                    }
                }
            }
            __syncthreads();
        }
    }

    if (tid < KK) ssc[tid] = tanhf(ssc[tid]);
    __syncthreads();

    {
        int j = tid;
        float csum = 0.f, cmax = -3.402823466e38f;
#pragma unroll 4
        for (int r = 0; r < KK; r++) {
            int row = sidx[r];
            float v = Xg[(long)row * 256 + j] * ssc[r];
            Xp[(long)g * KK * 256 + (long)r * 256 + j] = v;
            csum += v;
            cmax = fmaxf(cmax, v);
        }
        readout[(long)g * 1536 + roff + j] = csum;
        readout[(long)g * 1536 + roff + 256 + j] = cmax;
    }

    if (Aout) {
        for (int t = tid; t < KK * KK; t += 256) {
            int r = t / KK, c = t % KK;
            sAn[t] = Ag[(long)sidx[r] * NV + sidx[c]];
        }
        __syncthreads();
        for (int t = tid; t < KK * KK; t += 256) Aout[(long)g * KK * KK + t] = sAn[t];
        if (tid < KK) {
            float d = 0.f;
#pragma unroll
            for (int c = 0; c < KK; c++) d += sAn[tid * KK + c];
            normOut[(long)g * KK + tid] = rsqrtf(fmaxf(d, 1.f));
        }
    }
}

// ---------------- final head ---------------------------------------------------
__global__ void head_kernel(const float* __restrict__ H, const float* __restrict__ Wd2,
                            const float* __restrict__ bd2, float* __restrict__ out)
{
    int g = blockIdx.x;
    int o = threadIdx.x >> 5;
    int lane = threadIdx.x & 31;
    float acc = 0.f;
#pragma unroll
    for (int k = lane; k < 128; k += 32) acc += H[(long)g * 128 + k] * Wd2[k * 2 + o];
#pragma unroll
    for (int s = 16; s > 0; s >>= 1) acc += __shfl_down_sync(0xffffffffu, acc, s);
    if (lane == 0) {
        float z = acc + bd2[o];
        out[g * 2 + o] = 1.f / (1.f + expf(-z));
    }
}

// --------------------------------- launch --------------------------------------
extern "C" void kernel_launch(void* const* d_in, const int* in_sizes, int n_in,
                              void* d_out, int out_size)
{
    const float* feat = (const float*)d_in[0];
    const float* adj  = (const float*)d_in[1];
    const float* W0   = (const float*)d_in[2];
    const float* b0   = (const float*)d_in[3];
    const float* Ws0  = (const float*)d_in[4];
    const float* bs0  = (const float*)d_in[5];
    const float* W1   = (const float*)d_in[6];
    const float* b1   = (const float*)d_in[7];
    const float* Ws1  = (const float*)d_in[8];
    const float* bs1  = (const float*)d_in[9];
    const float* W2   = (const float*)d_in[10];
    const float* b2   = (const float*)d_in[11];
    const float* Ws2  = (const float*)d_in[12];
    const float* bs2  = (const float*)d_in[13];
    const float* Wd1  = (const float*)d_in[14];
    const float* bd1  = (const float*)d_in[15];
    const float* Wd2  = (const float*)d_in[16];
    const float* bd2  = (const float*)d_in[17];
    float* out = (float*)d_out;

    float *p_norm0, *p_Y, *p_X1, *p_spre, *p_Xp1, *p_A1, *p_norm1, *p_H1, *p_X2;
    float *p_Xp2, *p_A2, *p_norm2, *p_H2, *p_X3, *p_Xp3, *p_read, *p_h;
    unsigned char* p_cols; int* p_cnt;
    cudaGetSymbolAddress((void**)&p_norm0, g_norm0);
    cudaGetSymbolAddress((void**)&p_cols, g_cols);
    cudaGetSymbolAddress((void**)&p_cnt, g_cnt);
    cudaGetSymbolAddress((void**)&p_Y, g_Y);
    cudaGetSymbolAddress((void**)&p_X1, g_X1);
    cudaGetSymbolAddress((void**)&p_spre, g_spre);
    cudaGetSymbolAddress((void**)&p_Xp1, g_Xp1);
    cudaGetSymbolAddress((void**)&p_A1, g_A1);
    cudaGetSymbolAddress((void**)&p_norm1, g_norm1);
    cudaGetSymbolAddress((void**)&p_H1, g_H1);
    cudaGetSymbolAddress((void**)&p_X2, g_X2);
    cudaGetSymbolAddress((void**)&p_Xp2, g_Xp2);
    cudaGetSymbolAddress((void**)&p_A2, g_A2);
    cudaGetSymbolAddress((void**)&p_norm2, g_norm2);
    cudaGetSymbolAddress((void**)&p_H2, g_H2);
    cudaGetSymbolAddress((void**)&p_X3, g_X3);
    cudaGetSymbolAddress((void**)&p_Xp3, g_Xp3);
    cudaGetSymbolAddress((void**)&p_read, g_read);
    cudaGetSymbolAddress((void**)&p_h, g_h);

    cudaFuncSetAttribute(spmm_feat_kernel, cudaFuncAttributeMaxDynamicSharedMemorySize, 131072);

    // ---- layer 0 (reassociated): Y = norm.*(A@(norm.*x)); X1 = leaky(Y@W0 + b0)
    build_adj_kernel<<<G * NNODE / 8, 256>>>(adj, p_cols, p_cnt, p_norm0);
    spmm_feat_kernel<<<G, 256, 131072>>>(p_cols, p_cnt, feat, p_norm0, p_Y);
    sgemm_kernel<<<dim3(2, 2048, 1), 256>>>(p_Y, W0, p_X1, G * NNODE, DH, FIN,
                                            0, 0, 0, nullptr, 0, nullptr, 0, b0, 1,
                                            Ws0, p_spre);
    pool_kernel<256, 32><<<G, 256>>>(p_X1, adj, p_norm0, Ws0, bs0, p_cols, p_cnt,
                                     p_spre, p_Xp1, p_A1, p_norm1, p_read, 0);
    // ---- layer 1
    sgemm_kernel<<<dim3(2, 256, 1), 256>>>(p_Xp1, W1, p_H1, G * 32, DH, DH,
                                           0, 0, 0, p_norm1, 0, nullptr, 0, nullptr, 0,
                                           nullptr, nullptr);
    conv_small_kernel<32><<<G, 256>>>(p_A1, p_H1, p_norm1, b1, p_X2);
    pool_kernel<32, 16><<<G, 256>>>(p_X2, p_A1, p_norm1, Ws1, bs1, nullptr, nullptr,
                                    nullptr, p_Xp2, p_A2, p_norm2, p_read, 512);
    // ---- layer 2
    sgemm_kernel<<<dim3(2, 128, 1), 256>>>(p_Xp2, W2, p_H2, G * 16, DH, DH,
                                           0, 0, 0, p_norm2, 0, nullptr, 0, nullptr, 0,
                                           nullptr, nullptr);
    conv_small_kernel<16><<<G, 256>>>(p_A2, p_H2, p_norm2, b2, p_X3);
    pool_kernel<16, 8><<<G, 256>>>(p_X3, p_A2, p_norm2, Ws2, bs2, nullptr, nullptr,
                                   nullptr, p_Xp3, nullptr, nullptr, p_read, 1024);
    // ---- MLP head
    sgemm_kernel<<<dim3(1, 8, 1), 256>>>(p_read, Wd1, p_h, G, 128, 1536,
                                         0, 0, 0, nullptr, 0, nullptr, 0, bd1, 1,
                                         nullptr, nullptr);
    head_kernel<<<G, 64>>>(p_h, Wd2, bd2, out);
}